// round 2
// baseline (speedup 1.0000x reference)
#include <cuda_runtime.h>
#include <math.h>
#include <stdint.h>

#define NB 8
#define NE 1024
#define ND 512
#define NQKV 512
#define NH 8
#define NHD 64
#define NBH (NB*NH)         // 64
#define M_ROWS (NB*NE)      // 8192
#define SLAB (NE*NHD)       // 65536
#define LN_EPS 1e-5f
#define ATTN_SCALE 0.044194173824159216f   // 1/sqrt(512)

// ---------------- scratch (device globals; no runtime allocation) -------------
__device__ float g_q[NBH*SLAB];       // (B,H,E,HD) 16MB
__device__ float g_k[NBH*SLAB];
__device__ float g_v[NBH*SLAB];
__device__ float g_ctx[M_ROWS*NQKV];  // (B,E,H,HD) == (8192,512) 16MB

// ---------------- cp.async helpers -------------------------------------------
__device__ __forceinline__ void cp_async16(void* smem, const void* gmem) {
    uint32_t s = (uint32_t)__cvta_generic_to_shared(smem);
    asm volatile("cp.async.cg.shared.global [%0], [%1], 16;\n" :: "r"(s), "l"(gmem));
}
#define CP_COMMIT() asm volatile("cp.async.commit_group;\n" ::: "memory")
#define CP_WAIT0()  asm volatile("cp.async.wait_group 0;\n" ::: "memory")

// =============================================================================
// Shared GEMM core: C(128x128) = A(128xK) @ W(KxN128tile) double-buffered
// As: [2][128][20] m-major pitch 20 (conflict-free), Bs: [2][16][128]
// =============================================================================
#define AP 20

__device__ __forceinline__ void gemm_load_tiles(
    float (*As)[128][AP], float (*Bs)[16][128],
    int buf, const float* __restrict__ A, const float* __restrict__ W,
    int by, int bx, int kk, int lda, int ldw, int tid)
{
    // A tile: 128 rows x 16 k, 512 16B-chunks
    #pragma unroll
    for (int l = 0; l < 2; ++l) {
        int idx = l*256 + tid;
        int row = idx >> 2;          // 0..127
        int kc4 = (idx & 3) << 2;    // 0,4,8,12
        cp_async16(&As[buf][row][kc4], A + (size_t)(by*128 + row)*lda + kk + kc4);
    }
    // B tile: 16 k x 128 n
    #pragma unroll
    for (int l = 0; l < 2; ++l) {
        int idx = l*256 + tid;
        int row = idx >> 5;          // 0..15
        int n4  = (idx & 31) << 2;   // 0..124
        cp_async16(&Bs[buf][row][n4], W + (size_t)(kk + row)*ldw + bx*128 + n4);
    }
    CP_COMMIT();
}

__device__ __forceinline__ void gemm_compute(
    float (*As)[128][AP], float (*Bs)[16][128],
    int buf, int tx, int ty, float acc[8][8])
{
    #pragma unroll
    for (int k4 = 0; k4 < 16; k4 += 4) {
        float a[8][4];
        #pragma unroll
        for (int i = 0; i < 4; ++i) {
            float4 t0 = *(float4*)&As[buf][ty*4 + i][k4];
            a[i][0]=t0.x; a[i][1]=t0.y; a[i][2]=t0.z; a[i][3]=t0.w;
            float4 t1 = *(float4*)&As[buf][64 + ty*4 + i][k4];
            a[4+i][0]=t1.x; a[4+i][1]=t1.y; a[4+i][2]=t1.z; a[4+i][3]=t1.w;
        }
        #pragma unroll
        for (int ku = 0; ku < 4; ++ku) {
            float b[8];
            float4 b0 = *(float4*)&Bs[buf][k4+ku][tx*4];
            float4 b1 = *(float4*)&Bs[buf][k4+ku][64 + tx*4];
            b[0]=b0.x; b[1]=b0.y; b[2]=b0.z; b[3]=b0.w;
            b[4]=b1.x; b[5]=b1.y; b[6]=b1.z; b[7]=b1.w;
            #pragma unroll
            for (int i = 0; i < 8; ++i)
                #pragma unroll
                for (int j = 0; j < 8; ++j)
                    acc[i][j] = fmaf(a[i][ku], b[j], acc[i][j]);
        }
    }
}

// =============================================================================
// Kernel 1: QKV projection, scatter to (B,H,E,HD)
// =============================================================================
__global__ __launch_bounds__(256, 2) void gemm_qkv_kernel(
    const float* __restrict__ X,
    const float* __restrict__ Wq, const float* __restrict__ bq,
    const float* __restrict__ Wk, const float* __restrict__ bk,
    const float* __restrict__ Wv, const float* __restrict__ bv)
{
    const int t = blockIdx.z;
    const float* __restrict__ W    = (t==0) ? Wq : ((t==1) ? Wk : Wv);
    const float* __restrict__ bias = (t==0) ? bq : ((t==1) ? bk : bv);
    float* __restrict__ Y          = (t==0) ? g_q : ((t==1) ? g_k : g_v);

    const int bx = blockIdx.x, by = blockIdx.y;
    const int tid = threadIdx.x;
    const int tx = tid & 15, ty = tid >> 4;

    __shared__ float As[2][128][AP];
    __shared__ float Bs[2][16][128];

    float acc[8][8];
    #pragma unroll
    for (int i = 0; i < 8; ++i)
        #pragma unroll
        for (int j = 0; j < 8; ++j) acc[i][j] = 0.f;

    gemm_load_tiles(As, Bs, 0, X, W, by, bx, 0, ND, NQKV, tid);
    CP_WAIT0();
    __syncthreads();

    int buf = 0;
    for (int kk = 16; kk < ND; kk += 16) {
        gemm_load_tiles(As, Bs, buf ^ 1, X, W, by, bx, kk, ND, NQKV, tid);
        gemm_compute(As, Bs, buf, tx, ty, acc);
        CP_WAIT0();
        __syncthreads();
        buf ^= 1;
    }
    gemm_compute(As, Bs, buf, tx, ty, acc);

    // epilogue: bias + scatter to (B,H,E,HD)
    #pragma unroll
    for (int i = 0; i < 8; ++i) {
        int gr = by*128 + ((i < 4) ? (ty*4 + i) : (64 + ty*4 + i - 4));
        int bi = gr >> 10;
        int e  = gr & 1023;
        #pragma unroll
        for (int hj = 0; hj < 2; ++hj) {
            int gc0 = bx*128 + hj*64 + tx*4;
            int h   = gc0 >> 6;
            int hd0 = gc0 & 63;
            float4 r;
            r.x = acc[i][hj*4+0] + bias[gc0+0];
            r.y = acc[i][hj*4+1] + bias[gc0+1];
            r.z = acc[i][hj*4+2] + bias[gc0+2];
            r.w = acc[i][hj*4+3] + bias[gc0+3];
            *(float4*)(Y + ((size_t)(bi*NH + h)*NE + e)*NHD + hd0) = r;
        }
    }
}

// =============================================================================
// Kernel 2: LayerNorm over (E,HD) slab per (b,h) + affine + ReLU, in place.
// grid = (64, 3), 1024 threads.
// =============================================================================
__global__ __launch_bounds__(1024) void ln_kernel(
    const float* __restrict__ lw0, const float* __restrict__ lb0,
    const float* __restrict__ lw1, const float* __restrict__ lb1,
    const float* __restrict__ lw2, const float* __restrict__ lb2)
{
    const int t  = blockIdx.y;
    const int bh = blockIdx.x;
    float* __restrict__ Y        = (t==0) ? g_q : ((t==1) ? g_k : g_v);
    const float* __restrict__ lw = (t==0) ? lw0 : ((t==1) ? lw1 : lw2);
    const float* __restrict__ lb = (t==0) ? lb0 : ((t==1) ? lb1 : lb2);
    float* base = Y + (size_t)bh * SLAB;

    const int tid = threadIdx.x;
    float s = 0.f, s2 = 0.f;
    for (int i = tid*4; i < SLAB; i += 1024*4) {
        float4 v = *(const float4*)(base + i);
        s  += v.x + v.y + v.z + v.w;
        s2 += v.x*v.x + v.y*v.y + v.z*v.z + v.w*v.w;
    }
    #pragma unroll
    for (int o = 16; o > 0; o >>= 1) {
        s  += __shfl_xor_sync(0xffffffffu, s,  o);
        s2 += __shfl_xor_sync(0xffffffffu, s2, o);
    }
    __shared__ float rs[32], rs2[32], bc[2];
    int w = tid >> 5, lane = tid & 31;
    if (lane == 0) { rs[w] = s; rs2[w] = s2; }
    __syncthreads();
    if (w == 0) {
        s  = rs[lane];
        s2 = rs2[lane];
        #pragma unroll
        for (int o = 16; o > 0; o >>= 1) {
            s  += __shfl_xor_sync(0xffffffffu, s,  o);
            s2 += __shfl_xor_sync(0xffffffffu, s2, o);
        }
        if (lane == 0) {
            float mean = s * (1.f / SLAB);
            float var  = s2 * (1.f / SLAB) - mean*mean;
            bc[0] = mean;
            bc[1] = rsqrtf(var + LN_EPS);
        }
    }
    __syncthreads();
    const float mean = bc[0], rstd = bc[1];

    for (int i = tid*4; i < SLAB; i += 1024*4) {
        float4 v = *(const float4*)(base + i);
        float4 g = *(const float4*)(lw + i);
        float4 b = *(const float4*)(lb + i);
        v.x = fmaxf(0.f, (v.x - mean)*rstd*g.x + b.x);
        v.y = fmaxf(0.f, (v.y - mean)*rstd*g.y + b.y);
        v.z = fmaxf(0.f, (v.z - mean)*rstd*g.z + b.z);
        v.w = fmaxf(0.f, (v.w - mean)*rstd*g.w + b.w);
        *(float4*)(base + i) = v;
    }
}

// =============================================================================
// Kernel 3: flash attention per (b,h).  BQ = BKV = 128, HD = 64.
// grid = (E/128, B*H), 256 threads.
// =============================================================================
#define QS_PITCH 68
#define VS_PITCH 68
#define SS_PITCH 132
#define SMEM_ATTN ((128*QS_PITCH + 128*QS_PITCH + 128*VS_PITCH + 128*SS_PITCH)*4)

__global__ __launch_bounds__(256) void attn_kernel()
{
    extern __shared__ float sm[];
    float* Qs = sm;
    float* Ks = Qs + 128*QS_PITCH;
    float* Vs = Ks + 128*QS_PITCH;
    float* Ss = Vs + 128*VS_PITCH;

    const int bh = blockIdx.y;
    const int qb = blockIdx.x;
    const int tid = threadIdx.x;
    const int tx = tid & 15;
    const int ty = tid >> 4;
    const int r0 = ty * 8;

    const float* __restrict__ qg = g_q + (size_t)bh*SLAB + (size_t)qb*128*NHD;
    const float* __restrict__ kg = g_k + (size_t)bh*SLAB;
    const float* __restrict__ vg = g_v + (size_t)bh*SLAB;

    // load Q tile (scale folded in)
    #pragma unroll
    for (int l = 0; l < 8; ++l) {
        int idx = l*256 + tid;
        int row = idx >> 4;
        int c4  = (idx & 15) << 2;
        float4 v = *(const float4*)(qg + row*NHD + c4);
        Qs[row*QS_PITCH + c4 + 0] = v.x * ATTN_SCALE;
        Qs[row*QS_PITCH + c4 + 1] = v.y * ATTN_SCALE;
        Qs[row*QS_PITCH + c4 + 2] = v.z * ATTN_SCALE;
        Qs[row*QS_PITCH + c4 + 3] = v.w * ATTN_SCALE;
    }

    float m_i[8], l_i[8];
    float4 o[8];
    #pragma unroll
    for (int i = 0; i < 8; ++i) {
        m_i[i] = -INFINITY; l_i[i] = 0.f;
        o[i].x = o[i].y = o[i].z = o[i].w = 0.f;
    }

    for (int kt = 0; kt < NE/128; ++kt) {
        const float* kgt = kg + (size_t)kt*128*NHD;
        const float* vgt = vg + (size_t)kt*128*NHD;

        // stage K/V into registers BEFORE the barrier (hides L2 latency)
        float4 kreg[8], vreg[8];
        #pragma unroll
        for (int l = 0; l < 8; ++l) {
            int idx = l*256 + tid;
            int row = idx >> 4;
            int c4  = (idx & 15) << 2;
            kreg[l] = *(const float4*)(kgt + row*NHD + c4);
            vreg[l] = *(const float4*)(vgt + row*NHD + c4);
        }
        __syncthreads();   // previous iteration's Ks/Vs/Ss reads done
        #pragma unroll
        for (int l = 0; l < 8; ++l) {
            int idx = l*256 + tid;
            int row = idx >> 4;
            int c4  = (idx & 15) << 2;
            *(float4*)&Ks[row*QS_PITCH + c4] = kreg[l];
            *(float4*)&Vs[row*VS_PITCH + c4] = vreg[l];
        }
        __syncthreads();

        // ---- S = Q @ K^T  (vectorized over f in chunks of 4)
        float s[8][8];
        #pragma unroll
        for (int i = 0; i < 8; ++i)
            #pragma unroll
            for (int j = 0; j < 8; ++j) s[i][j] = 0.f;

        #pragma unroll
        for (int f = 0; f < NHD; f += 4) {
            float q[8][4], kk[8][4];
            #pragma unroll
            for (int i = 0; i < 8; ++i) {
                float4 tq = *(float4*)&Qs[(r0 + i)*QS_PITCH + f];
                q[i][0]=tq.x; q[i][1]=tq.y; q[i][2]=tq.z; q[i][3]=tq.w;
            }
            #pragma unroll
            for (int j = 0; j < 8; ++j) {
                float4 tk = *(float4*)&Ks[(tx + 16*j)*QS_PITCH + f];
                kk[j][0]=tk.x; kk[j][1]=tk.y; kk[j][2]=tk.z; kk[j][3]=tk.w;
            }
            #pragma unroll
            for (int fu = 0; fu < 4; ++fu)
                #pragma unroll
                for (int i = 0; i < 8; ++i)
                    #pragma unroll
                    for (int j = 0; j < 8; ++j)
                        s[i][j] = fmaf(q[i][fu], kk[j][fu], s[i][j]);
        }

        // ---- online softmax (row groups are 16 consecutive lanes)
        #pragma unroll
        for (int i = 0; i < 8; ++i) {
            float tm = s[i][0];
            #pragma unroll
            for (int j = 1; j < 8; ++j) tm = fmaxf(tm, s[i][j]);
            #pragma unroll
            for (int off = 8; off > 0; off >>= 1)
                tm = fmaxf(tm, __shfl_xor_sync(0xffffffffu, tm, off));
            float mn    = fmaxf(m_i[i], tm);
            float alpha = __expf(m_i[i] - mn);
            float rsum  = 0.f;
            #pragma unroll
            for (int j = 0; j < 8; ++j) {
                float p = __expf(s[i][j] - mn);
                s[i][j] = p;
                rsum += p;
            }
            #pragma unroll
            for (int off = 8; off > 0; off >>= 1)
                rsum += __shfl_xor_sync(0xffffffffu, rsum, off);
            l_i[i] = l_i[i]*alpha + rsum;
            m_i[i] = mn;
            o[i].x *= alpha; o[i].y *= alpha; o[i].z *= alpha; o[i].w *= alpha;
            #pragma unroll
            for (int j = 0; j < 8; ++j)
                Ss[(r0 + i)*SS_PITCH + tx + 16*j] = s[i][j];
        }
        __syncthreads();

        // ---- O += P @ V  (vectorized over c in chunks of 4)
        #pragma unroll 2
        for (int c = 0; c < 128; c += 4) {
            float4 v[4];
            #pragma unroll
            for (int r = 0; r < 4; ++r)
                v[r] = *(float4*)&Vs[(c + r)*VS_PITCH + tx*4];
            #pragma unroll
            for (int i = 0; i < 8; ++i) {
                float4 p4 = *(float4*)&Ss[(r0 + i)*SS_PITCH + c];
                o[i].x = fmaf(p4.x, v[0].x, o[i].x);
                o[i].y = fmaf(p4.x, v[0].y, o[i].y);
                o[i].z = fmaf(p4.x, v[0].z, o[i].z);
                o[i].w = fmaf(p4.x, v[0].w, o[i].w);
                o[i].x = fmaf(p4.y, v[1].x, o[i].x);
                o[i].y = fmaf(p4.y, v[1].y, o[i].y);
                o[i].z = fmaf(p4.y, v[1].z, o[i].z);
                o[i].w = fmaf(p4.y, v[1].w, o[i].w);
                o[i].x = fmaf(p4.z, v[2].x, o[i].x);
                o[i].y = fmaf(p4.z, v[2].y, o[i].y);
                o[i].z = fmaf(p4.z, v[2].z, o[i].z);
                o[i].w = fmaf(p4.z, v[2].w, o[i].w);
                o[i].x = fmaf(p4.w, v[3].x, o[i].x);
                o[i].y = fmaf(p4.w, v[3].y, o[i].y);
                o[i].z = fmaf(p4.w, v[3].z, o[i].z);
                o[i].w = fmaf(p4.w, v[3].w, o[i].w);
            }
        }
    }

    // epilogue: normalize and write to (B,E,H,HD)
    const int bi = bh >> 3;
    const int h  = bh & 7;
    #pragma unroll
    for (int i = 0; i < 8; ++i) {
        float inv = 1.f / l_i[i];
        int e = qb*128 + r0 + i;
        float4 r;
        r.x = o[i].x * inv; r.y = o[i].y * inv;
        r.z = o[i].z * inv; r.w = o[i].w * inv;
        *(float4*)(g_ctx + ((size_t)(bi*NE + e)*NH + h)*NHD + tx*4) = r;
    }
}

// =============================================================================
// Kernel 4: output projection  out = relu(ctx @ Wo + bo), (8192,512) row-major
// =============================================================================
__global__ __launch_bounds__(256, 2) void gemm_out_kernel(
    const float* __restrict__ Wo, const float* __restrict__ bo,
    float* __restrict__ out)
{
    const int bx = blockIdx.x, by = blockIdx.y;
    const int tid = threadIdx.x;
    const int tx = tid & 15, ty = tid >> 4;

    __shared__ float As[2][128][AP];
    __shared__ float Bs[2][16][128];

    float acc[8][8];
    #pragma unroll
    for (int i = 0; i < 8; ++i)
        #pragma unroll
        for (int j = 0; j < 8; ++j) acc[i][j] = 0.f;

    gemm_load_tiles(As, Bs, 0, g_ctx, Wo, by, bx, 0, NQKV, ND, tid);
    CP_WAIT0();
    __syncthreads();

    int buf = 0;
    for (int kk = 16; kk < NQKV; kk += 16) {
        gemm_load_tiles(As, Bs, buf ^ 1, g_ctx, Wo, by, bx, kk, NQKV, ND, tid);
        gemm_compute(As, Bs, buf, tx, ty, acc);
        CP_WAIT0();
        __syncthreads();
        buf ^= 1;
    }
    gemm_compute(As, Bs, buf, tx, ty, acc);

    #pragma unroll
    for (int i = 0; i < 8; ++i) {
        int gr = by*128 + ((i < 4) ? (ty*4 + i) : (64 + ty*4 + i - 4));
        #pragma unroll
        for (int hj = 0; hj < 2; ++hj) {
            int gc0 = bx*128 + hj*64 + tx*4;
            float4 r;
            r.x = fmaxf(0.f, acc[i][hj*4+0] + bo[gc0+0]);
            r.y = fmaxf(0.f, acc[i][hj*4+1] + bo[gc0+1]);
            r.z = fmaxf(0.f, acc[i][hj*4+2] + bo[gc0+2]);
            r.w = fmaxf(0.f, acc[i][hj*4+3] + bo[gc0+3]);
            *(float4*)(out + (size_t)gr*ND + gc0) = r;
        }
    }
}

// =============================================================================
extern "C" void kernel_launch(void* const* d_in, const int* in_sizes, int n_in,
                              void* d_out, int out_size)
{
    const float* features = (const float*)d_in[0];
    const float* Wq   = (const float*)d_in[1];
    const float* bq   = (const float*)d_in[2];
    const float* lnqw = (const float*)d_in[3];
    const float* lnqb = (const float*)d_in[4];
    const float* Wk   = (const float*)d_in[5];
    const float* bk   = (const float*)d_in[6];
    const float* lnkw = (const float*)d_in[7];
    const float* lnkb = (const float*)d_in[8];
    const float* Wv   = (const float*)d_in[9];
    const float* bv   = (const float*)d_in[10];
    const float* lnvw = (const float*)d_in[11];
    const float* lnvb = (const float*)d_in[12];
    const float* Wo   = (const float*)d_in[13];
    const float* bo   = (const float*)d_in[14];
    float* out = (float*)d_out;

    cudaFuncSetAttribute(attn_kernel,
                         cudaFuncAttributeMaxDynamicSharedMemorySize, SMEM_ATTN);

    gemm_qkv_kernel<<<dim3(NQKV/128, M_ROWS/128, 3), 256>>>(
        features, Wq, bq, Wk, bk, Wv, bv);
    ln_kernel<<<dim3(NBH, 3), 1024>>>(lnqw, lnqb, lnkw, lnkb, lnvw, lnvb);
    attn_kernel<<<dim3(NE/128, NBH), 256, SMEM_ATTN>>>();
    gemm_out_kernel<<<dim3(ND/128, M_ROWS/128), 256>>>(Wo, bo, out);
}

// round 3
// speedup vs baseline: 2.7187x; 2.7187x over previous
#include <cuda_runtime.h>
#include <math.h>
#include <stdint.h>

#define NB 8
#define NE 1024
#define ND 512
#define NQKV 512
#define NH 8
#define NHD 64
#define NBH (NB*NH)         // 64
#define M_ROWS (NB*NE)      // 8192
#define SLAB (NE*NHD)       // 65536
#define LN_EPS 1e-5f
#define ATTN_SCALE 0.044194173824159216f           // 1/sqrt(512)
#define SC2 (ATTN_SCALE * 1.4426950408889634f)     // scale * log2(e)

// ---------------- scratch (device globals; no runtime allocation) -------------
__device__ float g_q[NBH*SLAB];        // (B,H,E,HD), tf32-rounded after LN
__device__ float g_k[NBH*SLAB];
__device__ float g_v[NBH*SLAB];
__device__ float g_ctx[M_ROWS*NQKV];   // (B,E,H,HD), tf32-rounded
__device__ float g_xt[M_ROWS*ND];      // tf32-rounded features
__device__ float g_wq[ND*NQKV];        // tf32-rounded weights
__device__ float g_wk[ND*NQKV];
__device__ float g_wv[ND*NQKV];
__device__ float g_wo[NQKV*ND];

// ---------------- helpers ------------------------------------------------------
__device__ __forceinline__ float tf32r(float x) {
    uint32_t u;
    asm("cvt.rna.tf32.f32 %0, %1;" : "=r"(u) : "f"(x));
    return __uint_as_float(u);
}
__device__ __forceinline__ float exp2a(float x) {
    float y;
    asm("ex2.approx.ftz.f32 %0, %1;" : "=f"(y) : "f"(x));
    return y;
}
__device__ __forceinline__ void mma8(float c[4], const float a[4], const float b[2]) {
    asm volatile(
        "mma.sync.aligned.m16n8k8.row.col.f32.tf32.tf32.f32 "
        "{%0,%1,%2,%3}, {%4,%5,%6,%7}, {%8,%9}, {%0,%1,%2,%3};\n"
        : "+f"(c[0]), "+f"(c[1]), "+f"(c[2]), "+f"(c[3])
        : "r"(__float_as_uint(a[0])), "r"(__float_as_uint(a[1])),
          "r"(__float_as_uint(a[2])), "r"(__float_as_uint(a[3])),
          "r"(__float_as_uint(b[0])), "r"(__float_as_uint(b[1])));
}
__device__ __forceinline__ void cp_async16(void* smem, const void* gmem) {
    uint32_t s = (uint32_t)__cvta_generic_to_shared(smem);
    asm volatile("cp.async.cg.shared.global [%0], [%1], 16;\n" :: "r"(s), "l"(gmem));
}
#define CP_COMMIT() asm volatile("cp.async.commit_group;\n" ::: "memory")
#define CP_WAIT0()  asm volatile("cp.async.wait_group 0;\n" ::: "memory")

// =============================================================================
// Kernel 0: elementwise tf32 rounding (producers pay all cvt cost)
// =============================================================================
__global__ __launch_bounds__(256) void cvt_kernel(
    const float* __restrict__ src, float* __restrict__ dst, int n4)
{
    int i = blockIdx.x*blockDim.x + threadIdx.x;
    if (i < n4) {
        float4 v = ((const float4*)src)[i];
        v.x = tf32r(v.x); v.y = tf32r(v.y);
        v.z = tf32r(v.z); v.w = tf32r(v.w);
        ((float4*)dst)[i] = v;
    }
}

// =============================================================================
// tf32 GEMM core: 128x128 block, k-step 32, 256 threads = 8 warps (2x4),
// warp tile 64x32, m16n8k8 mma. Operands already tf32-rounded in gmem.
//   As: m-major [128][36] ((4qr+qc)%32 distinct -> conflict-free frag loads)
//   Bs: k-major [32][136] ((8qc+qr)%32 distinct)
// =============================================================================
#define GAP 36
#define GBP 136
#define GEMM_SMEM ((2*128*GAP + 2*32*GBP)*4)

__device__ __forceinline__ void g_load(
    float* As, float* Bs,
    const float* __restrict__ A, const float* __restrict__ B,
    int by, int bx, int kk, int lda, int ldb, int tid)
{
    #pragma unroll
    for (int l = 0; l < 4; ++l) {
        int idx = l*256 + tid;
        int row = idx >> 3, k4 = (idx & 7) << 2;
        cp_async16(As + row*GAP + k4, A + (size_t)(by*128 + row)*lda + kk + k4);
    }
    #pragma unroll
    for (int l = 0; l < 4; ++l) {
        int idx = l*256 + tid;
        int kr = idx >> 5, n4 = (idx & 31) << 2;
        cp_async16(Bs + kr*GBP + n4, B + (size_t)(kk + kr)*ldb + bx*128 + n4);
    }
    CP_COMMIT();
}

__device__ __forceinline__ void g_compute(
    const float* As, const float* Bs,
    int wr, int wc, int qr, int qc, float c[4][4][4])
{
    #pragma unroll
    for (int kb = 0; kb < 32; kb += 8) {
        float a[4][4], b[4][2];
        #pragma unroll
        for (int mt = 0; mt < 4; ++mt) {
            const float* ap = As + (wr*64 + mt*16 + qr)*GAP + kb + qc;
            a[mt][0] = ap[0];
            a[mt][1] = ap[8*GAP];
            a[mt][2] = ap[4];
            a[mt][3] = ap[8*GAP + 4];
        }
        #pragma unroll
        for (int nt = 0; nt < 4; ++nt) {
            const float* bp = Bs + (kb + qc)*GBP + wc*32 + nt*8 + qr;
            b[nt][0] = bp[0];
            b[nt][1] = bp[4*GBP];
            #pragma unroll
            for (int mt = 0; mt < 4; ++mt)
                mma8(c[mt][nt], a[mt], b[nt]);
        }
    }
}

// =============================================================================
// Kernel 1: QKV projection (tf32 mma), scatter to (B,H,E,HD), fp32 output
// =============================================================================
__global__ __launch_bounds__(256, 2) void gemm_qkv_kernel(
    const float* __restrict__ bq, const float* __restrict__ bk,
    const float* __restrict__ bv)
{
    extern __shared__ float dsm[];
    float* As0 = dsm;
    float* As1 = dsm + 128*GAP;
    float* Bs0 = dsm + 2*128*GAP;
    float* Bs1 = Bs0 + 32*GBP;

    const int t = blockIdx.z;
    const float* __restrict__ W    = (t==0) ? g_wq : ((t==1) ? g_wk : g_wv);
    const float* __restrict__ bias = (t==0) ? bq   : ((t==1) ? bk   : bv);
    float* __restrict__ Y          = (t==0) ? g_q  : ((t==1) ? g_k  : g_v);

    const int bx = blockIdx.x, by = blockIdx.y;
    const int tid = threadIdx.x;
    const int w = tid >> 5, lane = tid & 31;
    const int wr = w >> 2, wc = w & 3;
    const int qr = lane >> 2, qc = lane & 3;

    float c[4][4][4];
    #pragma unroll
    for (int i = 0; i < 4; ++i)
        #pragma unroll
        for (int j = 0; j < 4; ++j)
            #pragma unroll
            for (int r = 0; r < 4; ++r) c[i][j][r] = 0.f;

    g_load(As0, Bs0, g_xt, W, by, bx, 0, ND, NQKV, tid);
    CP_WAIT0();
    __syncthreads();

    int buf = 0;
    for (int kk = 32; kk < ND; kk += 32) {
        g_load(buf ? As0 : As1, buf ? Bs0 : Bs1, g_xt, W, by, bx, kk, ND, NQKV, tid);
        g_compute(buf ? As1 : As0, buf ? Bs1 : Bs0, wr, wc, qr, qc, c);
        CP_WAIT0();
        __syncthreads();
        buf ^= 1;
    }
    g_compute(buf ? As1 : As0, buf ? Bs1 : Bs0, wr, wc, qr, qc, c);

    #pragma unroll
    for (int mt = 0; mt < 4; ++mt) {
        #pragma unroll
        for (int nt = 0; nt < 4; ++nt) {
            int gr = by*128 + wr*64 + mt*16 + qr;
            int gc = bx*128 + wc*32 + nt*8 + 2*qc;
            int h  = gc >> 6, hd = gc & 63;
            float bx0 = bias[gc], bx1 = bias[gc+1];
            {
                int bi = gr >> 10, e = gr & 1023;
                float2 v = { c[mt][nt][0] + bx0, c[mt][nt][1] + bx1 };
                *(float2*)(Y + ((size_t)(bi*NH + h)*NE + e)*NHD + hd) = v;
            }
            {
                int gr2 = gr + 8;
                int bi = gr2 >> 10, e = gr2 & 1023;
                float2 v = { c[mt][nt][2] + bx0, c[mt][nt][3] + bx1 };
                *(float2*)(Y + ((size_t)(bi*NH + h)*NE + e)*NHD + hd) = v;
            }
        }
    }
}

// =============================================================================
// Kernel 2: LayerNorm over (E,HD) slab per (b,h) + affine + ReLU, in place,
// output tf32-rounded (feeds tensor-core attention directly).
// =============================================================================
__global__ __launch_bounds__(1024) void ln_kernel(
    const float* __restrict__ lw0, const float* __restrict__ lb0,
    const float* __restrict__ lw1, const float* __restrict__ lb1,
    const float* __restrict__ lw2, const float* __restrict__ lb2)
{
    const int t  = blockIdx.y;
    const int bh = blockIdx.x;
    float* __restrict__ Y        = (t==0) ? g_q : ((t==1) ? g_k : g_v);
    const float* __restrict__ lw = (t==0) ? lw0 : ((t==1) ? lw1 : lw2);
    const float* __restrict__ lb = (t==0) ? lb0 : ((t==1) ? lb1 : lb2);
    float* base = Y + (size_t)bh * SLAB;

    const int tid = threadIdx.x;
    float s = 0.f, s2 = 0.f;
    for (int i = tid*4; i < SLAB; i += 1024*4) {
        float4 v = *(const float4*)(base + i);
        s  += v.x + v.y + v.z + v.w;
        s2 += v.x*v.x + v.y*v.y + v.z*v.z + v.w*v.w;
    }
    #pragma unroll
    for (int o = 16; o > 0; o >>= 1) {
        s  += __shfl_xor_sync(0xffffffffu, s,  o);
        s2 += __shfl_xor_sync(0xffffffffu, s2, o);
    }
    __shared__ float rs[32], rs2[32], bc[2];
    int w = tid >> 5, lane = tid & 31;
    if (lane == 0) { rs[w] = s; rs2[w] = s2; }
    __syncthreads();
    if (w == 0) {
        s  = rs[lane];
        s2 = rs2[lane];
        #pragma unroll
        for (int o = 16; o > 0; o >>= 1) {
            s  += __shfl_xor_sync(0xffffffffu, s,  o);
            s2 += __shfl_xor_sync(0xffffffffu, s2, o);
        }
        if (lane == 0) {
            float mean = s * (1.f / SLAB);
            float var  = s2 * (1.f / SLAB) - mean*mean;
            bc[0] = mean;
            bc[1] = rsqrtf(var + LN_EPS);
        }
    }
    __syncthreads();
    const float mean = bc[0], rstd = bc[1];

    for (int i = tid*4; i < SLAB; i += 1024*4) {
        float4 v = *(const float4*)(base + i);
        float4 g = *(const float4*)(lw + i);
        float4 b = *(const float4*)(lb + i);
        v.x = tf32r(fmaxf(0.f, (v.x - mean)*rstd*g.x + b.x));
        v.y = tf32r(fmaxf(0.f, (v.y - mean)*rstd*g.y + b.y));
        v.z = tf32r(fmaxf(0.f, (v.z - mean)*rstd*g.z + b.z));
        v.w = tf32r(fmaxf(0.f, (v.w - mean)*rstd*g.w + b.w));
        *(float4*)(base + i) = v;
    }
}

// =============================================================================
// Kernel 3: flash attention (tf32 mma). grid=(8, 64), 256 thr = 8 warps.
// Warp tile = 16 rows x full 128 cols -> row softmax stays in one quad.
//   Qs/Ks: [128][68], Vs: [128][72], Ss: [128][132]  (all frag-conflict-free)
// =============================================================================
#define QP 68
#define VP 72
#define SP 132
#define ATTN_SMEM ((128*QP + 128*QP + 128*VP + 128*SP)*4)

__global__ __launch_bounds__(256, 1) void attn_kernel()
{
    extern __shared__ float sm[];
    float* Qs = sm;
    float* Ks = Qs + 128*QP;
    float* Vs = Ks + 128*QP;
    float* Ss = Vs + 128*VP;

    const int bh = blockIdx.y;
    const int qb = blockIdx.x;
    const int tid = threadIdx.x;
    const int w = tid >> 5, lane = tid & 31;
    const int qr = lane >> 2, qc = lane & 3;
    const int r0 = w*16 + qr;

    const float* __restrict__ qg = g_q + (size_t)bh*SLAB + (size_t)qb*128*NHD;
    const float* __restrict__ kg = g_k + (size_t)bh*SLAB;
    const float* __restrict__ vg = g_v + (size_t)bh*SLAB;

    // stage Q (already tf32-rounded, scale folded into exp2 later)
    #pragma unroll
    for (int l = 0; l < 8; ++l) {
        int idx = l*256 + tid;
        int row = idx >> 4, c4 = (idx & 15) << 2;
        *(float4*)(Qs + row*QP + c4) = *(const float4*)(qg + row*NHD + c4);
    }

    float o[8][4];
    #pragma unroll
    for (int nt = 0; nt < 8; ++nt)
        #pragma unroll
        for (int r = 0; r < 4; ++r) o[nt][r] = 0.f;
    float m0 = -INFINITY, m1 = -INFINITY, l0 = 0.f, l1 = 0.f;

    for (int kt = 0; kt < NE/128; ++kt) {
        __syncthreads();
        const float* kgt = kg + (size_t)kt*128*NHD;
        const float* vgt = vg + (size_t)kt*128*NHD;
        #pragma unroll
        for (int l = 0; l < 8; ++l) {
            int idx = l*256 + tid;
            int row = idx >> 4, c4 = (idx & 15) << 2;
            *(float4*)(Ks + row*QP + c4) = *(const float4*)(kgt + row*NHD + c4);
            *(float4*)(Vs + row*VP + c4) = *(const float4*)(vgt + row*NHD + c4);
        }
        __syncthreads();

        // ---- S = Q @ K^T : warp rows r0 block (16), all 128 key cols
        float s[16][4];
        #pragma unroll
        for (int nt = 0; nt < 16; ++nt)
            #pragma unroll
            for (int r = 0; r < 4; ++r) s[nt][r] = 0.f;

        #pragma unroll
        for (int kb = 0; kb < NHD; kb += 8) {
            float a[4];
            const float* ap = Qs + (w*16 + qr)*QP + kb + qc;
            a[0] = ap[0]; a[1] = ap[8*QP]; a[2] = ap[4]; a[3] = ap[8*QP + 4];
            #pragma unroll
            for (int nt = 0; nt < 16; ++nt) {
                const float* bp = Ks + (nt*8 + qr)*QP + kb + qc;
                float b[2] = { bp[0], bp[4] };
                mma8(s[nt], a, b);
            }
        }

        // ---- online softmax (rows r0 and r0+8; quad lanes share a row)
        float mx0 = s[0][0], mx1 = s[0][2];
        #pragma unroll
        for (int nt = 0; nt < 16; ++nt) {
            mx0 = fmaxf(mx0, fmaxf(s[nt][0], s[nt][1]));
            mx1 = fmaxf(mx1, fmaxf(s[nt][2], s[nt][3]));
        }
        mx0 = fmaxf(mx0, __shfl_xor_sync(0xffffffffu, mx0, 1));
        mx0 = fmaxf(mx0, __shfl_xor_sync(0xffffffffu, mx0, 2));
        mx1 = fmaxf(mx1, __shfl_xor_sync(0xffffffffu, mx1, 1));
        mx1 = fmaxf(mx1, __shfl_xor_sync(0xffffffffu, mx1, 2));
        float mn0 = fmaxf(m0, mx0), mn1 = fmaxf(m1, mx1);
        float al0 = exp2a((m0 - mn0)*SC2);
        float al1 = exp2a((m1 - mn1)*SC2);
        m0 = mn0; m1 = mn1;
        l0 *= al0; l1 *= al1;
        #pragma unroll
        for (int nt = 0; nt < 8; ++nt) {
            o[nt][0] *= al0; o[nt][1] *= al0;
            o[nt][2] *= al1; o[nt][3] *= al1;
        }
        const float base0 = mn0*SC2, base1 = mn1*SC2;
        #pragma unroll
        for (int nt = 0; nt < 16; ++nt) {
            float p0 = exp2a(fmaf(s[nt][0], SC2, -base0));
            float p1 = exp2a(fmaf(s[nt][1], SC2, -base0));
            float p2 = exp2a(fmaf(s[nt][2], SC2, -base1));
            float p3 = exp2a(fmaf(s[nt][3], SC2, -base1));
            l0 += p0 + p1;
            l1 += p2 + p3;
            int col = nt*8 + 2*qc;
            float2 v0 = { tf32r(p0), tf32r(p1) };
            float2 v1 = { tf32r(p2), tf32r(p3) };
            *(float2*)(Ss + r0*SP + col)       = v0;
            *(float2*)(Ss + (r0 + 8)*SP + col) = v1;
        }
        __syncthreads();

        // ---- O += P @ V
        #pragma unroll
        for (int kb = 0; kb < 128; kb += 8) {
            float a[4];
            const float* ap = Ss + (w*16 + qr)*SP + kb + qc;
            a[0] = ap[0]; a[1] = ap[8*SP]; a[2] = ap[4]; a[3] = ap[8*SP + 4];
            #pragma unroll
            for (int nt = 0; nt < 8; ++nt) {
                const float* bp = Vs + (kb + qc)*VP + nt*8 + qr;
                float b[2] = { bp[0], bp[4*VP] };
                mma8(o[nt], a, b);
            }
        }
    }

    // final row sums across the quad
    l0 += __shfl_xor_sync(0xffffffffu, l0, 1);
    l0 += __shfl_xor_sync(0xffffffffu, l0, 2);
    l1 += __shfl_xor_sync(0xffffffffu, l1, 1);
    l1 += __shfl_xor_sync(0xffffffffu, l1, 2);
    const float inv0 = 1.f / l0, inv1 = 1.f / l1;

    // epilogue -> g_ctx (B,E,H,HD), tf32-rounded for the output GEMM
    const int bi = bh >> 3;
    const int h  = bh & 7;
    #pragma unroll
    for (int nt = 0; nt < 8; ++nt) {
        int hd = nt*8 + 2*qc;
        {
            int e = qb*128 + r0;
            float2 v = { tf32r(o[nt][0]*inv0), tf32r(o[nt][1]*inv0) };
            *(float2*)(g_ctx + ((size_t)(bi*NE + e)*NH + h)*NHD + hd) = v;
        }
        {
            int e = qb*128 + r0 + 8;
            float2 v = { tf32r(o[nt][2]*inv1), tf32r(o[nt][3]*inv1) };
            *(float2*)(g_ctx + ((size_t)(bi*NE + e)*NH + h)*NHD + hd) = v;
        }
    }
}

// =============================================================================
// Kernel 4: output projection (tf32 mma) out = relu(ctx @ Wo + bo)
// =============================================================================
__global__ __launch_bounds__(256, 2) void gemm_out_kernel(
    const float* __restrict__ bo, float* __restrict__ out)
{
    extern __shared__ float dsm[];
    float* As0 = dsm;
    float* As1 = dsm + 128*GAP;
    float* Bs0 = dsm + 2*128*GAP;
    float* Bs1 = Bs0 + 32*GBP;

    const int bx = blockIdx.x, by = blockIdx.y;
    const int tid = threadIdx.x;
    const int w = tid >> 5, lane = tid & 31;
    const int wr = w >> 2, wc = w & 3;
    const int qr = lane >> 2, qc = lane & 3;

    float c[4][4][4];
    #pragma unroll
    for (int i = 0; i < 4; ++i)
        #pragma unroll
        for (int j = 0; j < 4; ++j)
            #pragma unroll
            for (int r = 0; r < 4; ++r) c[i][j][r] = 0.f;

    g_load(As0, Bs0, g_ctx, g_wo, by, bx, 0, NQKV, ND, tid);
    CP_WAIT0();
    __syncthreads();

    int buf = 0;
    for (int kk = 32; kk < NQKV; kk += 32) {
        g_load(buf ? As0 : As1, buf ? Bs0 : Bs1, g_ctx, g_wo, by, bx, kk, NQKV, ND, tid);
        g_compute(buf ? As1 : As0, buf ? Bs1 : Bs0, wr, wc, qr, qc, c);
        CP_WAIT0();
        __syncthreads();
        buf ^= 1;
    }
    g_compute(buf ? As1 : As0, buf ? Bs1 : Bs0, wr, wc, qr, qc, c);

    #pragma unroll
    for (int mt = 0; mt < 4; ++mt) {
        #pragma unroll
        for (int nt = 0; nt < 4; ++nt) {
            int gr = by*128 + wr*64 + mt*16 + qr;
            int gc = bx*128 + wc*32 + nt*8 + 2*qc;
            float bx0 = bo[gc], bx1 = bo[gc+1];
            float2 v0 = { fmaxf(0.f, c[mt][nt][0] + bx0),
                          fmaxf(0.f, c[mt][nt][1] + bx1) };
            float2 v1 = { fmaxf(0.f, c[mt][nt][2] + bx0),
                          fmaxf(0.f, c[mt][nt][3] + bx1) };
            *(float2*)(out + (size_t)gr*ND + gc)     = v0;
            *(float2*)(out + (size_t)(gr+8)*ND + gc) = v1;
        }
    }
}

// =============================================================================
extern "C" void kernel_launch(void* const* d_in, const int* in_sizes, int n_in,
                              void* d_out, int out_size)
{
    const float* features = (const float*)d_in[0];
    const float* Wq   = (const float*)d_in[1];
    const float* bq   = (const float*)d_in[2];
    const float* lnqw = (const float*)d_in[3];
    const float* lnqb = (const float*)d_in[4];
    const float* Wk   = (const float*)d_in[5];
    const float* bk   = (const float*)d_in[6];
    const float* lnkw = (const float*)d_in[7];
    const float* lnkb = (const float*)d_in[8];
    const float* Wv   = (const float*)d_in[9];
    const float* bv   = (const float*)d_in[10];
    const float* lnvw = (const float*)d_in[11];
    const float* lnvb = (const float*)d_in[12];
    const float* Wo   = (const float*)d_in[13];
    const float* bo   = (const float*)d_in[14];
    float* out = (float*)d_out;

    cudaFuncSetAttribute(attn_kernel,
                         cudaFuncAttributeMaxDynamicSharedMemorySize, ATTN_SMEM);
    cudaFuncSetAttribute(gemm_qkv_kernel,
                         cudaFuncAttributeMaxDynamicSharedMemorySize, GEMM_SMEM);
    cudaFuncSetAttribute(gemm_out_kernel,
                         cudaFuncAttributeMaxDynamicSharedMemorySize, GEMM_SMEM);

    // resolve device-global scratch addresses
    float *p_xt, *p_wq, *p_wk, *p_wv, *p_wo;
    cudaGetSymbolAddress((void**)&p_xt, g_xt);
    cudaGetSymbolAddress((void**)&p_wq, g_wq);
    cudaGetSymbolAddress((void**)&p_wk, g_wk);
    cudaGetSymbolAddress((void**)&p_wv, g_wv);
    cudaGetSymbolAddress((void**)&p_wo, g_wo);

    // tf32 pre-rounding of all GEMM operands
    cvt_kernel<<<(M_ROWS*ND/4 + 255)/256, 256>>>(features, p_xt, M_ROWS*ND/4);
    cvt_kernel<<<(ND*NQKV/4 + 255)/256, 256>>>(Wq, p_wq, ND*NQKV/4);
    cvt_kernel<<<(ND*NQKV/4 + 255)/256, 256>>>(Wk, p_wk, ND*NQKV/4);
    cvt_kernel<<<(ND*NQKV/4 + 255)/256, 256>>>(Wv, p_wv, ND*NQKV/4);
    cvt_kernel<<<(NQKV*ND/4 + 255)/256, 256>>>(Wo, p_wo, NQKV*ND/4);

    gemm_qkv_kernel<<<dim3(NQKV/128, M_ROWS/128, 3), 256, GEMM_SMEM>>>(bq, bk, bv);
    ln_kernel<<<dim3(NBH, 3), 1024>>>(lnqw, lnqb, lnkw, lnkb, lnvw, lnvb);
    attn_kernel<<<dim3(NE/128, NBH), 256, ATTN_SMEM>>>();
    gemm_out_kernel<<<dim3(ND/128, M_ROWS/128), 256, GEMM_SMEM>>>(bo, out);
}

// round 5
// speedup vs baseline: 3.0885x; 1.1361x over previous
#include <cuda_runtime.h>
#include <math.h>
#include <stdint.h>

#define NB 8
#define NE 1024
#define ND 512
#define NQKV 512
#define NH 8
#define NHD 64
#define NBH (NB*NH)         // 64
#define M_ROWS (NB*NE)      // 8192
#define SLAB (NE*NHD)       // 65536
#define LN_EPS 1e-5f
#define ATTN_SCALE 0.044194173824159216f           // 1/sqrt(512)
#define SC2 (ATTN_SCALE * 1.4426950408889634f)     // scale * log2(e)

// ---------------- scratch (device globals; no runtime allocation) -------------
__device__ float g_q[NBH*SLAB];        // (B,H,E,HD), tf32-rounded after LN
__device__ float g_k[NBH*SLAB];
__device__ float g_v[NBH*SLAB];
__device__ float g_ctx[M_ROWS*NQKV];   // (B,E,H,HD), tf32-rounded

// ---------------- helpers ------------------------------------------------------
__device__ __forceinline__ float tf32r(float x) {
    uint32_t u;
    asm("cvt.rna.tf32.f32 %0, %1;" : "=r"(u) : "f"(x));
    return __uint_as_float(u);
}
__device__ __forceinline__ float exp2a(float x) {
    float y;
    asm("ex2.approx.ftz.f32 %0, %1;" : "=f"(y) : "f"(x));
    return y;
}
__device__ __forceinline__ void mma8(float c[4], const float a[4], const float b[2]) {
    asm volatile(
        "mma.sync.aligned.m16n8k8.row.col.f32.tf32.tf32.f32 "
        "{%0,%1,%2,%3}, {%4,%5,%6,%7}, {%8,%9}, {%0,%1,%2,%3};\n"
        : "+f"(c[0]), "+f"(c[1]), "+f"(c[2]), "+f"(c[3])
        : "r"(__float_as_uint(a[0])), "r"(__float_as_uint(a[1])),
          "r"(__float_as_uint(a[2])), "r"(__float_as_uint(a[3])),
          "r"(__float_as_uint(b[0])), "r"(__float_as_uint(b[1])));
}
__device__ __forceinline__ void cp_async16(void* smem, const void* gmem) {
    uint32_t s = (uint32_t)__cvta_generic_to_shared(smem);
    asm volatile("cp.async.cg.shared.global [%0], [%1], 16;\n" :: "r"(s), "l"(gmem));
}
#define CP_COMMIT() asm volatile("cp.async.commit_group;\n" ::: "memory")
#define CP_WAIT0()  asm volatile("cp.async.wait_group 0;\n" ::: "memory")

// =============================================================================
// tf32 GEMM core: 128x128 block, k-step 32, 256 threads = 8 warps (2x4),
// warp tile 64x32, m16n8k8 mma. HW truncation handles fp32->tf32.
//   As: m-major [128][36], Bs: k-major [32][136]  (frag-conflict-free)
// =============================================================================
#define GAP 36
#define GBP 136
#define GEMM_SMEM ((2*128*GAP + 2*32*GBP)*4)

__device__ __forceinline__ void g_load(
    float* As, float* Bs,
    const float* __restrict__ A, const float* __restrict__ B,
    int by, int bx, int kk, int lda, int ldb, int tid)
{
    #pragma unroll
    for (int l = 0; l < 4; ++l) {
        int idx = l*256 + tid;
        int row = idx >> 3, k4 = (idx & 7) << 2;
        cp_async16(As + row*GAP + k4, A + (size_t)(by*128 + row)*lda + kk + k4);
    }
    #pragma unroll
    for (int l = 0; l < 4; ++l) {
        int idx = l*256 + tid;
        int kr = idx >> 5, n4 = (idx & 31) << 2;
        cp_async16(Bs + kr*GBP + n4, B + (size_t)(kk + kr)*ldb + bx*128 + n4);
    }
    CP_COMMIT();
}

__device__ __forceinline__ void g_compute(
    const float* As, const float* Bs,
    int wr, int wc, int qr, int qc, float c[4][4][4])
{
    #pragma unroll
    for (int kb = 0; kb < 32; kb += 8) {
        float a[4][4], b[4][2];
        #pragma unroll
        for (int mt = 0; mt < 4; ++mt) {
            const float* ap = As + (wr*64 + mt*16 + qr)*GAP + kb + qc;
            a[mt][0] = ap[0];
            a[mt][1] = ap[8*GAP];
            a[mt][2] = ap[4];
            a[mt][3] = ap[8*GAP + 4];
        }
        #pragma unroll
        for (int nt = 0; nt < 4; ++nt) {
            const float* bp = Bs + (kb + qc)*GBP + wc*32 + nt*8 + qr;
            b[nt][0] = bp[0];
            b[nt][1] = bp[4*GBP];
            #pragma unroll
            for (int mt = 0; mt < 4; ++mt)
                mma8(c[mt][nt], a[mt], b[nt]);
        }
    }
}

// =============================================================================
// Kernel 1: QKV projection (tf32 mma), scatter to (B,H,E,HD)
// =============================================================================
__global__ __launch_bounds__(256, 2) void gemm_qkv_kernel(
    const float* __restrict__ X,
    const float* __restrict__ Wq, const float* __restrict__ bq,
    const float* __restrict__ Wk, const float* __restrict__ bk,
    const float* __restrict__ Wv, const float* __restrict__ bv)
{
    extern __shared__ float dsm[];
    float* As0 = dsm;
    float* As1 = dsm + 128*GAP;
    float* Bs0 = dsm + 2*128*GAP;
    float* Bs1 = Bs0 + 32*GBP;

    const int t = blockIdx.z;
    const float* __restrict__ W    = (t==0) ? Wq : ((t==1) ? Wk : Wv);
    const float* __restrict__ bias = (t==0) ? bq : ((t==1) ? bk : bv);
    float* __restrict__ Y          = (t==0) ? g_q : ((t==1) ? g_k : g_v);

    const int bx = blockIdx.x, by = blockIdx.y;
    const int tid = threadIdx.x;
    const int w = tid >> 5, lane = tid & 31;
    const int wr = w >> 2, wc = w & 3;
    const int qr = lane >> 2, qc = lane & 3;

    float c[4][4][4];
    #pragma unroll
    for (int i = 0; i < 4; ++i)
        #pragma unroll
        for (int j = 0; j < 4; ++j)
            #pragma unroll
            for (int r = 0; r < 4; ++r) c[i][j][r] = 0.f;

    g_load(As0, Bs0, X, W, by, bx, 0, ND, NQKV, tid);
    CP_WAIT0();
    __syncthreads();

    int buf = 0;
    for (int kk = 32; kk < ND; kk += 32) {
        g_load(buf ? As0 : As1, buf ? Bs0 : Bs1, X, W, by, bx, kk, ND, NQKV, tid);
        g_compute(buf ? As1 : As0, buf ? Bs1 : Bs0, wr, wc, qr, qc, c);
        CP_WAIT0();
        __syncthreads();
        buf ^= 1;
    }
    g_compute(buf ? As1 : As0, buf ? Bs1 : Bs0, wr, wc, qr, qc, c);

    #pragma unroll
    for (int mt = 0; mt < 4; ++mt) {
        #pragma unroll
        for (int nt = 0; nt < 4; ++nt) {
            int gr = by*128 + wr*64 + mt*16 + qr;
            int gc = bx*128 + wc*32 + nt*8 + 2*qc;
            int h  = gc >> 6, hd = gc & 63;
            float bx0 = bias[gc], bx1 = bias[gc+1];
            {
                int bi = gr >> 10, e = gr & 1023;
                float2 v = { c[mt][nt][0] + bx0, c[mt][nt][1] + bx1 };
                *(float2*)(Y + ((size_t)(bi*NH + h)*NE + e)*NHD + hd) = v;
            }
            {
                int gr2 = gr + 8;
                int bi = gr2 >> 10, e = gr2 & 1023;
                float2 v = { c[mt][nt][2] + bx0, c[mt][nt][3] + bx1 };
                *(float2*)(Y + ((size_t)(bi*NH + h)*NE + e)*NHD + hd) = v;
            }
        }
    }
}

// =============================================================================
// Kernel 2: LayerNorm over (E,HD) slab per (b,h) + affine + ReLU, in place,
// output tf32-rounded.
// =============================================================================
__global__ __launch_bounds__(1024) void ln_kernel(
    const float* __restrict__ lw0, const float* __restrict__ lb0,
    const float* __restrict__ lw1, const float* __restrict__ lb1,
    const float* __restrict__ lw2, const float* __restrict__ lb2)
{
    const int t  = blockIdx.y;
    const int bh = blockIdx.x;
    float* __restrict__ Y        = (t==0) ? g_q : ((t==1) ? g_k : g_v);
    const float* __restrict__ lw = (t==0) ? lw0 : ((t==1) ? lw1 : lw2);
    const float* __restrict__ lb = (t==0) ? lb0 : ((t==1) ? lb1 : lb2);
    float* base = Y + (size_t)bh * SLAB;

    const int tid = threadIdx.x;
    float s = 0.f, s2 = 0.f;
    for (int i = tid*4; i < SLAB; i += 1024*4) {
        float4 v = *(const float4*)(base + i);
        s  += v.x + v.y + v.z + v.w;
        s2 += v.x*v.x + v.y*v.y + v.z*v.z + v.w*v.w;
    }
    #pragma unroll
    for (int o = 16; o > 0; o >>= 1) {
        s  += __shfl_xor_sync(0xffffffffu, s,  o);
        s2 += __shfl_xor_sync(0xffffffffu, s2, o);
    }
    __shared__ float rs[32], rs2[32], bc[2];
    int w = tid >> 5, lane = tid & 31;
    if (lane == 0) { rs[w] = s; rs2[w] = s2; }
    __syncthreads();
    if (w == 0) {
        s  = rs[lane];
        s2 = rs2[lane];
        #pragma unroll
        for (int o = 16; o > 0; o >>= 1) {
            s  += __shfl_xor_sync(0xffffffffu, s,  o);
            s2 += __shfl_xor_sync(0xffffffffu, s2, o);
        }
        if (lane == 0) {
            float mean = s * (1.f / SLAB);
            float var  = s2 * (1.f / SLAB) - mean*mean;
            bc[0] = mean;
            bc[1] = rsqrtf(var + LN_EPS);
        }
    }
    __syncthreads();
    const float mean = bc[0], rstd = bc[1];

    for (int i = tid*4; i < SLAB; i += 1024*4) {
        float4 v = *(const float4*)(base + i);
        float4 g = *(const float4*)(lw + i);
        float4 b = *(const float4*)(lb + i);
        v.x = tf32r(fmaxf(0.f, (v.x - mean)*rstd*g.x + b.x));
        v.y = tf32r(fmaxf(0.f, (v.y - mean)*rstd*g.y + b.y));
        v.z = tf32r(fmaxf(0.f, (v.z - mean)*rstd*g.z + b.z));
        v.w = tf32r(fmaxf(0.f, (v.w - mean)*rstd*g.w + b.w));
        *(float4*)(base + i) = v;
    }
}

// =============================================================================
// Kernel 3: flash attention (tf32 mma). grid=(8,64), 256 thr = 8 warps.
// Q fragments in registers; K/V double-buffered via cp.async (2-stage).
//   Kb[2]: [128][68], Vb[2]: [128][72], Ss: [128][132]  (206 KB)
// Pipeline: wait(tile kt) -> sync (also retires PV reads of kt-1)
//           -> prefetch kt+1 into the retired buffer -> compute on kt.
// =============================================================================
#define KP 68
#define VP 72
#define SP 132
#define ATTN_SMEM ((2*128*KP + 2*128*VP + 128*SP)*4)

__device__ __forceinline__ void attn_load_kv(
    float* Kb, float* Vb, const float* __restrict__ kgt,
    const float* __restrict__ vgt, int tid)
{
    #pragma unroll
    for (int l = 0; l < 8; ++l) {
        int idx = l*256 + tid;
        int row = idx >> 4, c4 = (idx & 15) << 2;
        cp_async16(Kb + row*KP + c4, kgt + row*NHD + c4);
        cp_async16(Vb + row*VP + c4, vgt + row*NHD + c4);
    }
    CP_COMMIT();
}

__global__ __launch_bounds__(256, 1) void attn_kernel()
{
    extern __shared__ float sm[];
    float* Kb0 = sm;
    float* Kb1 = Kb0 + 128*KP;
    float* Vb0 = Kb1 + 128*KP;
    float* Vb1 = Vb0 + 128*VP;
    float* Ss  = Vb1 + 128*VP;

    const int bh = blockIdx.y;
    const int qb = blockIdx.x;
    const int tid = threadIdx.x;
    const int w = tid >> 5, lane = tid & 31;
    const int qr = lane >> 2, qc = lane & 3;
    const int r0 = w*16 + qr;

    const float* __restrict__ qg = g_q + (size_t)bh*SLAB + (size_t)qb*128*NHD;
    const float* __restrict__ kg = g_k + (size_t)bh*SLAB;
    const float* __restrict__ vg = g_v + (size_t)bh*SLAB;

    // kick off K/V tile 0 while we stage Q
    attn_load_kv(Kb0, Vb0, kg, vg, tid);

    // stage Q tile into Ss, then lift fragments into registers
    #pragma unroll
    for (int l = 0; l < 8; ++l) {
        int idx = l*256 + tid;
        int row = idx >> 4, c4 = (idx & 15) << 2;
        *(float4*)(Ss + row*SP + c4) = *(const float4*)(qg + row*NHD + c4);
    }
    __syncthreads();
    float qf[8][4];
    #pragma unroll
    for (int kbi = 0; kbi < 8; ++kbi) {
        const float* ap = Ss + r0*SP + kbi*8 + qc;
        qf[kbi][0] = ap[0];
        qf[kbi][1] = ap[8*SP];
        qf[kbi][2] = ap[4];
        qf[kbi][3] = ap[8*SP + 4];
    }

    float o[8][4];
    #pragma unroll
    for (int nt = 0; nt < 8; ++nt)
        #pragma unroll
        for (int r = 0; r < 4; ++r) o[nt][r] = 0.f;
    float m0 = -INFINITY, m1 = -INFINITY, l0 = 0.f, l1 = 0.f;

    for (int kt = 0; kt < NE/128; ++kt) {
        const int buf = kt & 1;
        float* Kc = buf ? Kb1 : Kb0;
        float* Vc = buf ? Vb1 : Vb0;

        CP_WAIT0();        // tile kt data landed (only one group in flight)
        __syncthreads();   // publish tile kt; also retires PV reads of kt-1

        if (kt + 1 < NE/128) {
            // safe: !buf buffers fully retired by the barrier above
            attn_load_kv(buf ? Kb0 : Kb1, buf ? Vb0 : Vb1,
                         kg + (size_t)(kt+1)*128*NHD,
                         vg + (size_t)(kt+1)*128*NHD, tid);
        }

        // ---- S = Q @ K^T
        float s[16][4];
        #pragma unroll
        for (int nt = 0; nt < 16; ++nt)
            #pragma unroll
            for (int r = 0; r < 4; ++r) s[nt][r] = 0.f;

        #pragma unroll
        for (int kbi = 0; kbi < 8; ++kbi) {
            #pragma unroll
            for (int nt = 0; nt < 16; ++nt) {
                const float* bp = Kc + (nt*8 + qr)*KP + kbi*8 + qc;
                float b[2] = { bp[0], bp[4] };
                mma8(s[nt], qf[kbi], b);
            }
        }

        // ---- online softmax (rows r0 and r0+8; quad lanes share a row)
        float mx0 = s[0][0], mx1 = s[0][2];
        #pragma unroll
        for (int nt = 0; nt < 16; ++nt) {
            mx0 = fmaxf(mx0, fmaxf(s[nt][0], s[nt][1]));
            mx1 = fmaxf(mx1, fmaxf(s[nt][2], s[nt][3]));
        }
        mx0 = fmaxf(mx0, __shfl_xor_sync(0xffffffffu, mx0, 1));
        mx0 = fmaxf(mx0, __shfl_xor_sync(0xffffffffu, mx0, 2));
        mx1 = fmaxf(mx1, __shfl_xor_sync(0xffffffffu, mx1, 1));
        mx1 = fmaxf(mx1, __shfl_xor_sync(0xffffffffu, mx1, 2));
        float mn0 = fmaxf(m0, mx0), mn1 = fmaxf(m1, mx1);
        float al0 = exp2a((m0 - mn0)*SC2);
        float al1 = exp2a((m1 - mn1)*SC2);
        m0 = mn0; m1 = mn1;
        l0 *= al0; l1 *= al1;
        #pragma unroll
        for (int nt = 0; nt < 8; ++nt) {
            o[nt][0] *= al0; o[nt][1] *= al0;
            o[nt][2] *= al1; o[nt][3] *= al1;
        }
        const float base0 = mn0*SC2, base1 = mn1*SC2;
        #pragma unroll
        for (int nt = 0; nt < 16; ++nt) {
            float p0 = exp2a(fmaf(s[nt][0], SC2, -base0));
            float p1 = exp2a(fmaf(s[nt][1], SC2, -base0));
            float p2 = exp2a(fmaf(s[nt][2], SC2, -base1));
            float p3 = exp2a(fmaf(s[nt][3], SC2, -base1));
            l0 += p0 + p1;
            l1 += p2 + p3;
            int col = nt*8 + 2*qc;
            float2 v0 = { tf32r(p0), tf32r(p1) };
            float2 v1 = { tf32r(p2), tf32r(p3) };
            *(float2*)(Ss + r0*SP + col)       = v0;
            *(float2*)(Ss + (r0 + 8)*SP + col) = v1;
        }
        __syncthreads();

        // ---- O += P @ V
        #pragma unroll
        for (int kb = 0; kb < 128; kb += 8) {
            float a[4];
            const float* ap = Ss + r0*SP + kb + qc;
            a[0] = ap[0]; a[1] = ap[8*SP]; a[2] = ap[4]; a[3] = ap[8*SP + 4];
            #pragma unroll
            for (int nt = 0; nt < 8; ++nt) {
                const float* bp = Vc + (kb + qc)*VP + nt*8 + qr;
                float b[2] = { bp[0], bp[4*VP] };
                mma8(o[nt], a, b);
            }
        }
    }

    // final row sums across the quad
    l0 += __shfl_xor_sync(0xffffffffu, l0, 1);
    l0 += __shfl_xor_sync(0xffffffffu, l0, 2);
    l1 += __shfl_xor_sync(0xffffffffu, l1, 1);
    l1 += __shfl_xor_sync(0xffffffffu, l1, 2);
    const float inv0 = 1.f / l0, inv1 = 1.f / l1;

    // epilogue -> g_ctx (B,E,H,HD), tf32-rounded for the output GEMM
    const int bi = bh >> 3;
    const int h  = bh & 7;
    #pragma unroll
    for (int nt = 0; nt < 8; ++nt) {
        int hd = nt*8 + 2*qc;
        {
            int e = qb*128 + r0;
            float2 v = { tf32r(o[nt][0]*inv0), tf32r(o[nt][1]*inv0) };
            *(float2*)(g_ctx + ((size_t)(bi*NE + e)*NH + h)*NHD + hd) = v;
        }
        {
            int e = qb*128 + r0 + 8;
            float2 v = { tf32r(o[nt][2]*inv1), tf32r(o[nt][3]*inv1) };
            *(float2*)(g_ctx + ((size_t)(bi*NE + e)*NH + h)*NHD + hd) = v;
        }
    }
}

// =============================================================================
// Kernel 4: output projection (tf32 mma) out = relu(ctx @ Wo + bo)
// =============================================================================
__global__ __launch_bounds__(256, 2) void gemm_out_kernel(
    const float* __restrict__ Wo, const float* __restrict__ bo,
    float* __restrict__ out)
{
    extern __shared__ float dsm[];
    float* As0 = dsm;
    float* As1 = dsm + 128*GAP;
    float* Bs0 = dsm + 2*128*GAP;
    float* Bs1 = Bs0 + 32*GBP;

    const int bx = blockIdx.x, by = blockIdx.y;
    const int tid = threadIdx.x;
    const int w = tid >> 5, lane = tid & 31;
    const int wr = w >> 2, wc = w & 3;
    const int qr = lane >> 2, qc = lane & 3;

    float c[4][4][4];
    #pragma unroll
    for (int i = 0; i < 4; ++i)
        #pragma unroll
        for (int j = 0; j < 4; ++j)
            #pragma unroll
            for (int r = 0; r < 4; ++r) c[i][j][r] = 0.f;

    g_load(As0, Bs0, g_ctx, Wo, by, bx, 0, NQKV, ND, tid);
    CP_WAIT0();
    __syncthreads();

    int buf = 0;
    for (int kk = 32; kk < NQKV; kk += 32) {
        g_load(buf ? As0 : As1, buf ? Bs0 : Bs1, g_ctx, Wo, by, bx, kk, NQKV, ND, tid);
        g_compute(buf ? As1 : As0, buf ? Bs1 : Bs0, wr, wc, qr, qc, c);
        CP_WAIT0();
        __syncthreads();
        buf ^= 1;
    }
    g_compute(buf ? As1 : As0, buf ? Bs1 : Bs0, wr, wc, qr, qc, c);

    #pragma unroll
    for (int mt = 0; mt < 4; ++mt) {
        #pragma unroll
        for (int nt = 0; nt < 4; ++nt) {
            int gr = by*128 + wr*64 + mt*16 + qr;
            int gc = bx*128 + wc*32 + nt*8 + 2*qc;
            float bx0 = bo[gc], bx1 = bo[gc+1];
            float2 v0 = { fmaxf(0.f, c[mt][nt][0] + bx0),
                          fmaxf(0.f, c[mt][nt][1] + bx1) };
            float2 v1 = { fmaxf(0.f, c[mt][nt][2] + bx0),
                          fmaxf(0.f, c[mt][nt][3] + bx1) };
            *(float2*)(out + (size_t)gr*ND + gc)     = v0;
            *(float2*)(out + (size_t)(gr+8)*ND + gc) = v1;
        }
    }
}

// =============================================================================
extern "C" void kernel_launch(void* const* d_in, const int* in_sizes, int n_in,
                              void* d_out, int out_size)
{
    const float* features = (const float*)d_in[0];
    const float* Wq   = (const float*)d_in[1];
    const float* bq   = (const float*)d_in[2];
    const float* lnqw = (const float*)d_in[3];
    const float* lnqb = (const float*)d_in[4];
    const float* Wk   = (const float*)d_in[5];
    const float* bk   = (const float*)d_in[6];
    const float* lnkw = (const float*)d_in[7];
    const float* lnkb = (const float*)d_in[8];
    const float* Wv   = (const float*)d_in[9];
    const float* bv   = (const float*)d_in[10];
    const float* lnvw = (const float*)d_in[11];
    const float* lnvb = (const float*)d_in[12];
    const float* Wo   = (const float*)d_in[13];
    const float* bo   = (const float*)d_in[14];
    float* out = (float*)d_out;

    cudaFuncSetAttribute(attn_kernel,
                         cudaFuncAttributeMaxDynamicSharedMemorySize, ATTN_SMEM);
    cudaFuncSetAttribute(gemm_qkv_kernel,
                         cudaFuncAttributeMaxDynamicSharedMemorySize, GEMM_SMEM);
    cudaFuncSetAttribute(gemm_out_kernel,
                         cudaFuncAttributeMaxDynamicSharedMemorySize, GEMM_SMEM);

    gemm_qkv_kernel<<<dim3(NQKV/128, M_ROWS/128, 3), 256, GEMM_SMEM>>>(
        features, Wq, bq, Wk, bk, Wv, bv);
    ln_kernel<<<dim3(NBH, 3), 1024>>>(lnqw, lnqb, lnkw, lnkb, lnvw, lnvb);
    attn_kernel<<<dim3(NE/128, NBH), 256, ATTN_SMEM>>>();
    gemm_out_kernel<<<dim3(ND/128, M_ROWS/128), 256, GEMM_SMEM>>>(Wo, bo, out);
}